// round 13
// baseline (speedup 1.0000x reference)
#include <cuda_runtime.h>
#include <math.h>
#include <stdint.h>

#define Bx 4
#define Sx 128
#define Dx 256
#define Hx 8

static __device__ float g_Vp [2][Bx*Sx*Dx];   // V partials (K halves), no bias
static __device__ float g_QKp[2][Bx*Sx*64];   // QK partials, no bias
static __device__ float g_AO [Bx*Sx*Dx];      // attention output (pre-Wo)

// ---------------------------------------------------------------------------
// Half-K GEMM (R10/R11-proven, k1=9.9us): C = sum_{k in chunk kc} A*B^T (NT)
// 32m x 32n, 256 thr. Warp w: n-group ng=w&3 (8 n), k4-parity kp=w>>2.
// As/Bs [32][33] f4 padded. qk mode gathers B rows from Wq|Wk:
//   col -> h=col>>3, side=(col>>2)&1, w=col&3, row = h*32+w.
// ---------------------------------------------------------------------------
__device__ __forceinline__ void gemm_half(
    const float4* __restrict__ A4,
    const float4* __restrict__ Bq4, const float4* __restrict__ Bk4,
    float* __restrict__ C, int m0, int n0, int cstride, int qk, int kc,
    float* sm)
{
    float4* As = (float4*)sm;
    float4* Bs = (float4*)sm + 32*33;
    const int tid  = threadIdx.x;
    const int lane = tid & 31;
    const int w    = tid >> 5;
    const int ng   = w & 3;
    const int kp   = w >> 2;

    float acc[8][2];
#pragma unroll
    for (int j = 0; j < 8; j++) { acc[j][0] = 0.f; acc[j][1] = 0.f; }

    const float4* Ap = As + lane*33 + kp;
    const float4* Bp = Bs + (ng*8)*33 + kp;

#pragma unroll
    for (int t = 0; t < 4; t++) {
        const int idx = tid + (t << 8);
        const int r = idx >> 5, c = idx & 31;
        As[r*33 + c] = A4[(m0 + r)*64 + (kc << 5) + c];
        int brow;
        const float4* bp;
        if (qk) {
            const int col = n0 + r;
            brow = ((col >> 3)*32) + (col & 3);
            bp = ((col >> 2) & 1) ? Bk4 : Bq4;
        } else {
            brow = n0 + r;
            bp = Bq4;
        }
        Bs[r*33 + c] = bp[brow*64 + (kc << 5) + c];
    }
    __syncthreads();

#pragma unroll 4
    for (int k4 = 0; k4 < 16; k4++) {
        const float4 a = Ap[k4*2];
#pragma unroll
        for (int j = 0; j < 8; j++) {
            const float4 b = Bp[j*33 + k4*2];
            acc[j][0] = fmaf(a.x, b.x, acc[j][0]);
            acc[j][1] = fmaf(a.y, b.y, acc[j][1]);
            acc[j][0] = fmaf(a.z, b.z, acc[j][0]);
            acc[j][1] = fmaf(a.w, b.w, acc[j][1]);
        }
    }
    __syncthreads();

    // cross-parity reduction through smem (17-pad: conflict-free)
    float* red = sm;
    if (kp == 1) {
#pragma unroll
        for (int j = 0; j < 8; j++) {
            red[(ng*32 + lane)*17 + j*2    ] = acc[j][0];
            red[(ng*32 + lane)*17 + j*2 + 1] = acc[j][1];
        }
    }
    __syncthreads();
    if (kp == 0) {
        const float* rp = &red[(ng*32 + lane)*17];
        float o[8];
#pragma unroll
        for (int j = 0; j < 8; j++)
            o[j] = acc[j][0] + acc[j][1] + rp[j*2] + rp[j*2 + 1];
        float* cp = &C[(m0 + lane)*cstride + n0 + ng*8];
        *(float4*)cp       = make_float4(o[0], o[1], o[2], o[3]);
        *(float4*)(cp + 4) = make_float4(o[4], o[5], o[6], o[7]);
    }
}

// ---------------------------------------------------------------------------
// Kernel 1 (R11-measured 9.9us): V-GEMM (256 blocks: 128 tiles x 2 K-halves)
// + QK-GEMM (64 blocks: 32 tiles x 2 K-halves).
// ---------------------------------------------------------------------------
__global__ void __launch_bounds__(256, 3) k1_gemms(
    const float* __restrict__ x,
    const float* __restrict__ Wq, const float* __restrict__ Wk,
    const float* __restrict__ Wv)
{
    __shared__ float sm[8448];    // 33KB
    const int bx = blockIdx.x;
    if (bx < 256) {
        const int tile = bx >> 1, kc = bx & 1;
        gemm_half((const float4*)x, (const float4*)Wv, nullptr,
                  g_Vp[kc], (tile >> 3) << 5, (tile & 7) << 5, 256, 0, kc, sm);
    } else {
        const int q = bx - 256;
        const int tile = q >> 1, kc = q & 1;
        gemm_half((const float4*)x, (const float4*)Wq, (const float4*)Wk,
                  g_QKp[kc], (tile >> 1) << 5, (tile & 1) << 5, 64, 1, kc, sm);
    }
}

// ---------------------------------------------------------------------------
// Kernel 2 (R10-proven): attention. 128 blocks = (bh, 32-row i-group),
// 256 threads. Sums K-split partials + biases while staging, inline trig,
// single-pass softmax (scores bounded |s| <= 0.177).
// score(i,j) = prod_{w=1..3}( cos(th_w)cos(q_iw) - sin(th_w)sin(q_iw)cos(k_jw) )
// ---------------------------------------------------------------------------
__global__ void __launch_bounds__(256) attn_kernel(
    const float* __restrict__ ap,
    const float* __restrict__ bq, const float* __restrict__ bk,
    const float* __restrict__ bv)
{
    const int bx = blockIdx.x;
    const int ig = bx & 3;
    const int bh = bx >> 2;
    const int b = bh >> 3, h = bh & 7;

    __shared__ float4 Vs[1024];      // [j][p]
    __shared__ float4 CKs[128];
    __shared__ float  AB[32*6];
    __shared__ float  E[128*33];     // [j][il], pad 33
    __shared__ float  Psum[32*9];
    __shared__ float  Sinv[32];

    const int tid = threadIdx.x;
    const float4* V0 = (const float4*)g_Vp[0];
    const float4* V1 = (const float4*)g_Vp[1];
#pragma unroll
    for (int t = 0; t < 4; t++) {
        const int idx = tid + (t << 8);
        const int j = idx >> 3, p = idx & 7;
        const int gi = (b*Sx + j)*64 + h*8 + p;
        const float4 a  = V0[gi];
        const float4 c  = V1[gi];
        const float4 bb = *(const float4*)&bv[h*32 + p*4];
        Vs[idx] = make_float4(a.x + c.x + bb.x, a.y + c.y + bb.y,
                              a.z + c.z + bb.z, a.w + c.w + bb.w);
    }

    const float PI = 3.14159265358979323846f;
    if (tid < 128) {
        // k-side trig for row j
        const int j = tid;
        const int base = (b*Sx + j)*64 + h*8 + 4;
        float v[4];
#pragma unroll
        for (int q = 0; q < 4; q++)
            v[q] = g_QKp[0][base + q] + g_QKp[1][base + q] + bk[h*32 + q];
        const float mn = fminf(fminf(v[0], v[1]), fminf(v[2], v[3]));
        const float mx = fmaxf(fmaxf(v[0], v[1]), fmaxf(v[2], v[3]));
        const float sc = PI / (mx - mn + 1e-8f);
        CKs[j] = make_float4(cosf((v[1] - mn)*sc), cosf((v[2] - mn)*sc),
                             cosf((v[3] - mn)*sc), 0.f);
    } else if (tid < 160) {
        // q-side trig for row i
        const int il = tid - 128;
        const int i  = (ig << 5) + il;
        const int base = (b*Sx + i)*64 + h*8;
        float v[4];
#pragma unroll
        for (int q = 0; q < 4; q++)
            v[q] = g_QKp[0][base + q] + g_QKp[1][base + q] + bq[h*32 + q];
        const float mn = fminf(fminf(v[0], v[1]), fminf(v[2], v[3]));
        const float mx = fmaxf(fmaxf(v[0], v[1]), fmaxf(v[2], v[3]));
        const float sc = PI / (mx - mn + 1e-8f);
#pragma unroll
        for (int w = 0; w < 3; w++) {
            float sn, cs;
            sincosf((v[w + 1] - mn)*sc, &sn, &cs);
            const float th = ap[w + 1];
            AB[il*6 + w*2 + 0] = cosf(th) * cs;
            AB[il*6 + w*2 + 1] = sinf(th) * sn;
        }
    }
    __syncthreads();

    const int il = tid & 31;
    const int i  = (ig << 5) + il;

    // phase 1: exp scores; jg = tid>>5 handles 16 j's
    {
        const int jg = tid >> 5;
        const float A1 = AB[il*6+0], B1 = AB[il*6+1];
        const float A2 = AB[il*6+2], B2 = AB[il*6+3];
        const float A3 = AB[il*6+4], B3 = AB[il*6+5];
        const float SCALE = 0.17677669529663687f;   // 1/sqrt(32)
        float s = 0.f;
#pragma unroll
        for (int jj = 0; jj < 16; jj++) {
            const int j = (jg << 4) + jj;
            const float4 ck = CKs[j];
            const float sc = (A1 - B1*ck.x) * (A2 - B2*ck.y) * (A3 - B3*ck.z);
            const float e = __expf(sc * SCALE);
            E[j*33 + il] = e;
            s += e;
        }
        Psum[il*9 + jg] = s;
    }
    __syncthreads();
    if (tid < 32) {
        float s = 0.f;
#pragma unroll
        for (int jg = 0; jg < 8; jg++) s += Psum[tid*9 + jg];
        Sinv[tid] = 1.0f / s;
    }
    __syncthreads();

    // phase 2: p = tid>>5 owns one float4 dim-group (broadcast V loads)
    {
        const int p = tid >> 5;
        float4 o = make_float4(0.f, 0.f, 0.f, 0.f);
#pragma unroll 8
        for (int j = 0; j < 128; j++) {
            const float e = E[j*33 + il];
            const float4 v = Vs[(j << 3) + p];
            o.x = fmaf(e, v.x, o.x);
            o.y = fmaf(e, v.y, o.y);
            o.z = fmaf(e, v.z, o.z);
            o.w = fmaf(e, v.w, o.w);
        }
        const float inv = Sinv[il];
        o.x *= inv; o.y *= inv; o.z *= inv; o.w *= inv;
        ((float4*)g_AO)[(b*Sx + i)*64 + h*8 + p] = o;
    }
}

// ---------------------------------------------------------------------------
// Kernel 3 (R9-proven): out = g_AO @ Wo.T + bo. Full K=256, 128 blocks,
// double-buffered K-chunks (chunk-1 LDG prefetched under chunk-0 compute),
// plain STG epilogue with bias. No atomics, no extra kernel.
// ---------------------------------------------------------------------------
__global__ void __launch_bounds__(256) k3_ogemm(
    const float* __restrict__ Wo, const float* __restrict__ bo,
    float* __restrict__ out)
{
    __shared__ float sm[8448];
    float4* As = (float4*)sm;
    float4* Bs = (float4*)sm + 32*33;

    const int tile = blockIdx.x;
    const int m0 = (tile >> 3) << 5;
    const int n0 = (tile & 7) << 5;
    const int tid  = threadIdx.x;
    const int lane = tid & 31;
    const int w    = tid >> 5;
    const int ng   = w & 3;
    const int kp   = w >> 2;

    const float4* A4 = (const float4*)g_AO;
    const float4* B4 = (const float4*)Wo;

    float acc[8][2];
#pragma unroll
    for (int j = 0; j < 8; j++) { acc[j][0] = 0.f; acc[j][1] = 0.f; }

    const float4* Ap = As + lane*33 + kp;
    const float4* Bp = Bs + (ng*8)*33 + kp;

    int srow[4], scol[4];
#pragma unroll
    for (int t = 0; t < 4; t++) {
        const int idx = tid + (t << 8);
        srow[t] = idx >> 5;
        scol[t] = idx & 31;
    }

    float4 ra[4], rb[4];
    // prefetch + stage chunk 0
#pragma unroll
    for (int t = 0; t < 4; t++) {
        ra[t] = A4[(m0 + srow[t])*64 + scol[t]];
        rb[t] = B4[(n0 + srow[t])*64 + scol[t]];
    }
#pragma unroll
    for (int t = 0; t < 4; t++) {
        As[srow[t]*33 + scol[t]] = ra[t];
        Bs[srow[t]*33 + scol[t]] = rb[t];
    }
    __syncthreads();

    // prefetch chunk 1 (overlaps chunk-0 compute)
#pragma unroll
    for (int t = 0; t < 4; t++) {
        ra[t] = A4[(m0 + srow[t])*64 + 32 + scol[t]];
        rb[t] = B4[(n0 + srow[t])*64 + 32 + scol[t]];
    }

#pragma unroll 4
    for (int k4 = 0; k4 < 16; k4++) {
        const float4 a = Ap[k4*2];
#pragma unroll
        for (int j = 0; j < 8; j++) {
            const float4 b = Bp[j*33 + k4*2];
            acc[j][0] = fmaf(a.x, b.x, acc[j][0]);
            acc[j][1] = fmaf(a.y, b.y, acc[j][1]);
            acc[j][0] = fmaf(a.z, b.z, acc[j][0]);
            acc[j][1] = fmaf(a.w, b.w, acc[j][1]);
        }
    }
    __syncthreads();
#pragma unroll
    for (int t = 0; t < 4; t++) {
        As[srow[t]*33 + scol[t]] = ra[t];
        Bs[srow[t]*33 + scol[t]] = rb[t];
    }
    __syncthreads();
#pragma unroll 4
    for (int k4 = 0; k4 < 16; k4++) {
        const float4 a = Ap[k4*2];
#pragma unroll
        for (int j = 0; j < 8; j++) {
            const float4 b = Bp[j*33 + k4*2];
            acc[j][0] = fmaf(a.x, b.x, acc[j][0]);
            acc[j][1] = fmaf(a.y, b.y, acc[j][1]);
            acc[j][0] = fmaf(a.z, b.z, acc[j][0]);
            acc[j][1] = fmaf(a.w, b.w, acc[j][1]);
        }
    }
    __syncthreads();

    float* red = sm;
    if (kp == 1) {
#pragma unroll
        for (int j = 0; j < 8; j++) {
            red[(ng*32 + lane)*17 + j*2    ] = acc[j][0];
            red[(ng*32 + lane)*17 + j*2 + 1] = acc[j][1];
        }
    }
    __syncthreads();
    if (kp == 0) {
        const int n = n0 + ng*8;
        const float* rp = &red[(ng*32 + lane)*17];
        float o[8];
#pragma unroll
        for (int j = 0; j < 8; j++)
            o[j] = acc[j][0] + acc[j][1] + rp[j*2] + rp[j*2 + 1] + bo[n + j];
        float* cp = &out[(m0 + lane)*256 + n];
        *(float4*)cp       = make_float4(o[0], o[1], o[2], o[3]);
        *(float4*)(cp + 4) = make_float4(o[4], o[5], o[6], o[7]);
    }
}

// ---------------------------------------------------------------------------
extern "C" void kernel_launch(void* const* d_in, const int* in_sizes, int n_in,
                              void* d_out, int out_size)
{
    const float* x  = (const float*)d_in[0];
    const float* Wq = (const float*)d_in[1];
    const float* bq = (const float*)d_in[2];
    const float* Wk = (const float*)d_in[3];
    const float* bk = (const float*)d_in[4];
    const float* Wv = (const float*)d_in[5];
    const float* bv = (const float*)d_in[6];
    const float* Wo = (const float*)d_in[7];
    const float* bo = (const float*)d_in[8];
    const float* ap = (const float*)d_in[9];
    float* out = (float*)d_out;

    k1_gemms<<<320, 256>>>(x, Wq, Wk, Wv);
    attn_kernel<<<128, 256>>>(ap, bq, bk, bv);
    k3_ogemm<<<128, 256>>>(Wo, bo, out);
}

// round 14
// speedup vs baseline: 1.3253x; 1.3253x over previous
#include <cuda_runtime.h>
#include <math.h>
#include <stdint.h>

#define Bx 4
#define Sx 128
#define Dx 256
#define Hx 8

static __device__ float g_Vp [4][Bx*Sx*Dx];   // V partials (K quarters), no bias
static __device__ float g_QKp[4][Bx*Sx*64];   // QK partials, no bias
static __device__ float g_AO [Bx*Sx*Dx];      // attention output (pre-Wo)

// ---------------------------------------------------------------------------
// Quarter-K GEMM: C = sum_{k in 64-chunk kc} A[m][k]*B[n][k]  (NT)
// 32m x 32n tile, 256 thr. Warp w: n-group ng=w&3 (8 n), k4-parity kp=w>>2.
// As/Bs [32][17] float4 (addr stride 68 floats -> bank 4*lane mod 32,
// conflict-free a-loads; b-loads warp-uniform broadcast).
// qk mode gathers B rows from Wq|Wk:
//   col -> h=col>>3, side=(col>>2)&1, w=col&3, row = h*32+w.
// ---------------------------------------------------------------------------
__device__ __forceinline__ void gemm_q(
    const float4* __restrict__ A4,
    const float4* __restrict__ Bq4, const float4* __restrict__ Bk4,
    float* __restrict__ C, int m0, int n0, int cstride, int qk, int kc,
    float* sm)
{
    float4* As = (float4*)sm;            // [32][17] f4 = 8704B
    float4* Bs = (float4*)sm + 544;      // [32][17] f4
    const int tid  = threadIdx.x;
    const int lane = tid & 31;
    const int w    = tid >> 5;
    const int ng   = w & 3;
    const int kp   = w >> 2;

    float acc[8][2];
#pragma unroll
    for (int j = 0; j < 8; j++) { acc[j][0] = 0.f; acc[j][1] = 0.f; }

    const float4* Ap = As + lane*17 + kp;
    const float4* Bp = Bs + (ng*8)*17 + kp;

    // stage the 64-wide K chunk: 32 rows x 16 float4 each for A and B
#pragma unroll
    for (int t = 0; t < 2; t++) {
        const int idx = tid + (t << 8);
        const int r = idx >> 4, c = idx & 15;
        As[r*17 + c] = A4[(m0 + r)*64 + (kc << 4) + c];
        int brow;
        const float4* bp;
        if (qk) {
            const int col = n0 + r;
            brow = ((col >> 3)*32) + (col & 3);
            bp = ((col >> 2) & 1) ? Bk4 : Bq4;
        } else {
            brow = n0 + r;
            bp = Bq4;
        }
        Bs[r*17 + c] = bp[brow*64 + (kc << 4) + c];
    }
    __syncthreads();

#pragma unroll
    for (int k4 = 0; k4 < 8; k4++) {
        const float4 a = Ap[k4*2];
#pragma unroll
        for (int j = 0; j < 8; j++) {
            const float4 b = Bp[j*17 + k4*2];
            acc[j][0] = fmaf(a.x, b.x, acc[j][0]);
            acc[j][1] = fmaf(a.y, b.y, acc[j][1]);
            acc[j][0] = fmaf(a.z, b.z, acc[j][0]);
            acc[j][1] = fmaf(a.w, b.w, acc[j][1]);
        }
    }
    __syncthreads();

    // cross-parity reduction through smem (17-float rows: conflict-free)
    float* red = sm;
    if (kp == 1) {
#pragma unroll
        for (int j = 0; j < 8; j++) {
            red[(ng*32 + lane)*17 + j*2    ] = acc[j][0];
            red[(ng*32 + lane)*17 + j*2 + 1] = acc[j][1];
        }
    }
    __syncthreads();
    if (kp == 0) {
        const float* rp = &red[(ng*32 + lane)*17];
        float o[8];
#pragma unroll
        for (int j = 0; j < 8; j++)
            o[j] = acc[j][0] + acc[j][1] + rp[j*2] + rp[j*2 + 1];
        float* cp = &C[(m0 + lane)*cstride + n0 + ng*8];
        *(float4*)cp       = make_float4(o[0], o[1], o[2], o[3]);
        *(float4*)(cp + 4) = make_float4(o[4], o[5], o[6], o[7]);
    }
}

// ---------------------------------------------------------------------------
// Kernel 1: 640 blocks (~4.3/SM):
//   [0,512)   V-GEMM:  128 tiles x 4 K-quarters
//   [512,640) QK-GEMM:  32 tiles x 4 K-quarters
// ---------------------------------------------------------------------------
__global__ void __launch_bounds__(256, 4) k1_gemms(
    const float* __restrict__ x,
    const float* __restrict__ Wq, const float* __restrict__ Wk,
    const float* __restrict__ Wv)
{
    __shared__ float sm[4352];   // 17.4KB
    const int bx = blockIdx.x;
    if (bx < 512) {
        const int tile = bx >> 2, kc = bx & 3;
        gemm_q((const float4*)x, (const float4*)Wv, nullptr,
               g_Vp[kc], (tile >> 3) << 5, (tile & 7) << 5, 256, 0, kc, sm);
    } else {
        const int q = bx - 512;
        const int tile = q >> 2, kc = q & 3;
        gemm_q((const float4*)x, (const float4*)Wq, (const float4*)Wk,
               g_QKp[kc], (tile >> 1) << 5, (tile & 1) << 5, 64, 1, kc, sm);
    }
}

// ---------------------------------------------------------------------------
// Kernel 2: attention (proven body). 128 blocks = (bh, 32-row i-group),
// 256 threads. Sums 4 K-split partials + biases while staging, inline trig,
// single-pass softmax (scores bounded |s| <= 0.177).
// score(i,j) = prod_{w=1..3}( cos(th_w)cos(q_iw) - sin(th_w)sin(q_iw)cos(k_jw) )
// ---------------------------------------------------------------------------
__global__ void __launch_bounds__(256) attn_kernel(
    const float* __restrict__ ap,
    const float* __restrict__ bq, const float* __restrict__ bk,
    const float* __restrict__ bv)
{
    const int bx = blockIdx.x;
    const int ig = bx & 3;
    const int bh = bx >> 2;
    const int b = bh >> 3, h = bh & 7;

    __shared__ float4 Vs[1024];      // [j][p]
    __shared__ float4 CKs[128];
    __shared__ float  AB[32*6];
    __shared__ float  E[128*33];     // [j][il], pad 33
    __shared__ float  Psum[32*9];
    __shared__ float  Sinv[32];

    const int tid = threadIdx.x;
    const float4* V0 = (const float4*)g_Vp[0];
    const float4* V1 = (const float4*)g_Vp[1];
    const float4* V2 = (const float4*)g_Vp[2];
    const float4* V3 = (const float4*)g_Vp[3];
#pragma unroll
    for (int t = 0; t < 4; t++) {
        const int idx = tid + (t << 8);
        const int j = idx >> 3, p = idx & 7;
        const int gi = (b*Sx + j)*64 + h*8 + p;
        const float4 a0 = V0[gi];
        const float4 a1 = V1[gi];
        const float4 a2 = V2[gi];
        const float4 a3 = V3[gi];
        const float4 bb = *(const float4*)&bv[h*32 + p*4];
        Vs[idx] = make_float4(a0.x + a1.x + a2.x + a3.x + bb.x,
                              a0.y + a1.y + a2.y + a3.y + bb.y,
                              a0.z + a1.z + a2.z + a3.z + bb.z,
                              a0.w + a1.w + a2.w + a3.w + bb.w);
    }

    const float PI = 3.14159265358979323846f;
    if (tid < 128) {
        // k-side trig for row j
        const int j = tid;
        const int base = (b*Sx + j)*64 + h*8 + 4;
        float v[4];
#pragma unroll
        for (int q = 0; q < 4; q++)
            v[q] = g_QKp[0][base + q] + g_QKp[1][base + q]
                 + g_QKp[2][base + q] + g_QKp[3][base + q] + bk[h*32 + q];
        const float mn = fminf(fminf(v[0], v[1]), fminf(v[2], v[3]));
        const float mx = fmaxf(fmaxf(v[0], v[1]), fmaxf(v[2], v[3]));
        const float sc = PI / (mx - mn + 1e-8f);
        CKs[j] = make_float4(cosf((v[1] - mn)*sc), cosf((v[2] - mn)*sc),
                             cosf((v[3] - mn)*sc), 0.f);
    } else if (tid < 160) {
        // q-side trig for row i
        const int il = tid - 128;
        const int i  = (ig << 5) + il;
        const int base = (b*Sx + i)*64 + h*8;
        float v[4];
#pragma unroll
        for (int q = 0; q < 4; q++)
            v[q] = g_QKp[0][base + q] + g_QKp[1][base + q]
                 + g_QKp[2][base + q] + g_QKp[3][base + q] + bq[h*32 + q];
        const float mn = fminf(fminf(v[0], v[1]), fminf(v[2], v[3]));
        const float mx = fmaxf(fmaxf(v[0], v[1]), fmaxf(v[2], v[3]));
        const float sc = PI / (mx - mn + 1e-8f);
#pragma unroll
        for (int w = 0; w < 3; w++) {
            float sn, cs;
            sincosf((v[w + 1] - mn)*sc, &sn, &cs);
            const float th = ap[w + 1];
            AB[il*6 + w*2 + 0] = cosf(th) * cs;
            AB[il*6 + w*2 + 1] = sinf(th) * sn;
        }
    }
    __syncthreads();

    const int il = tid & 31;
    const int i  = (ig << 5) + il;

    // phase 1: exp scores; jg = tid>>5 handles 16 j's
    {
        const int jg = tid >> 5;
        const float A1 = AB[il*6+0], B1 = AB[il*6+1];
        const float A2 = AB[il*6+2], B2 = AB[il*6+3];
        const float A3 = AB[il*6+4], B3 = AB[il*6+5];
        const float SCALE = 0.17677669529663687f;   // 1/sqrt(32)
        float s = 0.f;
#pragma unroll
        for (int jj = 0; jj < 16; jj++) {
            const int j = (jg << 4) + jj;
            const float4 ck = CKs[j];
            const float sc = (A1 - B1*ck.x) * (A2 - B2*ck.y) * (A3 - B3*ck.z);
            const float e = __expf(sc * SCALE);
            E[j*33 + il] = e;
            s += e;
        }
        Psum[il*9 + jg] = s;
    }
    __syncthreads();
    if (tid < 32) {
        float s = 0.f;
#pragma unroll
        for (int jg = 0; jg < 8; jg++) s += Psum[tid*9 + jg];
        Sinv[tid] = 1.0f / s;
    }
    __syncthreads();

    // phase 2: p = tid>>5 owns one float4 dim-group (broadcast V loads)
    {
        const int p = tid >> 5;
        float4 o = make_float4(0.f, 0.f, 0.f, 0.f);
#pragma unroll 8
        for (int j = 0; j < 128; j++) {
            const float e = E[j*33 + il];
            const float4 v = Vs[(j << 3) + p];
            o.x = fmaf(e, v.x, o.x);
            o.y = fmaf(e, v.y, o.y);
            o.z = fmaf(e, v.z, o.z);
            o.w = fmaf(e, v.w, o.w);
        }
        const float inv = Sinv[il];
        o.x *= inv; o.y *= inv; o.z *= inv; o.w *= inv;
        ((float4*)g_AO)[(b*Sx + i)*64 + h*8 + p] = o;
    }
}

// ---------------------------------------------------------------------------
// Kernel 3 (R9-proven): out = g_AO @ Wo.T + bo. Full K=256, 128 blocks,
// double-buffered K-chunks, plain STG epilogue with bias.
// ---------------------------------------------------------------------------
__global__ void __launch_bounds__(256) k3_ogemm(
    const float* __restrict__ Wo, const float* __restrict__ bo,
    float* __restrict__ out)
{
    __shared__ float sm[8448];
    float4* As = (float4*)sm;
    float4* Bs = (float4*)sm + 32*33;

    const int tile = blockIdx.x;
    const int m0 = (tile >> 3) << 5;
    const int n0 = (tile & 7) << 5;
    const int tid  = threadIdx.x;
    const int lane = tid & 31;
    const int w    = tid >> 5;
    const int ng   = w & 3;
    const int kp   = w >> 2;

    const float4* A4 = (const float4*)g_AO;
    const float4* B4 = (const float4*)Wo;

    float acc[8][2];
#pragma unroll
    for (int j = 0; j < 8; j++) { acc[j][0] = 0.f; acc[j][1] = 0.f; }

    const float4* Ap = As + lane*33 + kp;
    const float4* Bp = Bs + (ng*8)*33 + kp;

    int srow[4], scol[4];
#pragma unroll
    for (int t = 0; t < 4; t++) {
        const int idx = tid + (t << 8);
        srow[t] = idx >> 5;
        scol[t] = idx & 31;
    }

    float4 ra[4], rb[4];
#pragma unroll
    for (int t = 0; t < 4; t++) {
        ra[t] = A4[(m0 + srow[t])*64 + scol[t]];
        rb[t] = B4[(n0 + srow[t])*64 + scol[t]];
    }
#pragma unroll
    for (int t = 0; t < 4; t++) {
        As[srow[t]*33 + scol[t]] = ra[t];
        Bs[srow[t]*33 + scol[t]] = rb[t];
    }
    __syncthreads();

#pragma unroll
    for (int t = 0; t < 4; t++) {
        ra[t] = A4[(m0 + srow[t])*64 + 32 + scol[t]];
        rb[t] = B4[(n0 + srow[t])*64 + 32 + scol[t]];
    }

#pragma unroll 4
    for (int k4 = 0; k4 < 16; k4++) {
        const float4 a = Ap[k4*2];
#pragma unroll
        for (int j = 0; j < 8; j++) {
            const float4 b = Bp[j*33 + k4*2];
            acc[j][0] = fmaf(a.x, b.x, acc[j][0]);
            acc[j][1] = fmaf(a.y, b.y, acc[j][1]);
            acc[j][0] = fmaf(a.z, b.z, acc[j][0]);
            acc[j][1] = fmaf(a.w, b.w, acc[j][1]);
        }
    }
    __syncthreads();
#pragma unroll
    for (int t = 0; t < 4; t++) {
        As[srow[t]*33 + scol[t]] = ra[t];
        Bs[srow[t]*33 + scol[t]] = rb[t];
    }
    __syncthreads();
#pragma unroll 4
    for (int k4 = 0; k4 < 16; k4++) {
        const float4 a = Ap[k4*2];
#pragma unroll
        for (int j = 0; j < 8; j++) {
            const float4 b = Bp[j*33 + k4*2];
            acc[j][0] = fmaf(a.x, b.x, acc[j][0]);
            acc[j][1] = fmaf(a.y, b.y, acc[j][1]);
            acc[j][0] = fmaf(a.z, b.z, acc[j][0]);
            acc[j][1] = fmaf(a.w, b.w, acc[j][1]);
        }
    }
    __syncthreads();

    float* red = sm;
    if (kp == 1) {
#pragma unroll
        for (int j = 0; j < 8; j++) {
            red[(ng*32 + lane)*17 + j*2    ] = acc[j][0];
            red[(ng*32 + lane)*17 + j*2 + 1] = acc[j][1];
        }
    }
    __syncthreads();
    if (kp == 0) {
        const int n = n0 + ng*8;
        const float* rp = &red[(ng*32 + lane)*17];
        float o[8];
#pragma unroll
        for (int j = 0; j < 8; j++)
            o[j] = acc[j][0] + acc[j][1] + rp[j*2] + rp[j*2 + 1] + bo[n + j];
        float* cp = &out[(m0 + lane)*256 + n];
        *(float4*)cp       = make_float4(o[0], o[1], o[2], o[3]);
        *(float4*)(cp + 4) = make_float4(o[4], o[5], o[6], o[7]);
    }
}

// ---------------------------------------------------------------------------
extern "C" void kernel_launch(void* const* d_in, const int* in_sizes, int n_in,
                              void* d_out, int out_size)
{
    const float* x  = (const float*)d_in[0];
    const float* Wq = (const float*)d_in[1];
    const float* bq = (const float*)d_in[2];
    const float* Wk = (const float*)d_in[3];
    const float* bk = (const float*)d_in[4];
    const float* Wv = (const float*)d_in[5];
    const float* bv = (const float*)d_in[6];
    const float* Wo = (const float*)d_in[7];
    const float* bo = (const float*)d_in[8];
    const float* ap = (const float*)d_in[9];
    float* out = (float*)d_out;

    k1_gemms<<<640, 256>>>(x, Wq, Wk, Wv);
    attn_kernel<<<128, 256>>>(ap, bq, bk, bv);
    k3_ogemm<<<128, 256>>>(Wo, bo, out);
}

// round 15
// speedup vs baseline: 1.3372x; 1.0089x over previous
#include <cuda_runtime.h>
#include <math.h>
#include <stdint.h>

#define Bx 4
#define Sx 128
#define Dx 256
#define Hx 8

static __device__ float g_Vp [4][Bx*Sx*Dx];   // V partials (K quarters), no bias
static __device__ float g_QKp[4][Bx*Sx*64];   // QK partials, no bias

// ---------------------------------------------------------------------------
// Quarter-K GEMM (R14-proven, k1 = 9.7us @ occ 39%):
// C = sum_{k in 64-chunk kc} A[m][k]*B[n][k]  (NT). 32m x 32n, 256 thr.
// Warp w: n-group ng=w&3, k4-parity kp=w>>2. As/Bs [32][17] float4.
// qk mode gathers B rows from Wq|Wk: col -> h=col>>3, side=(col>>2)&1,
// w=col&3, row = h*32+w.
// ---------------------------------------------------------------------------
__device__ __forceinline__ void gemm_q(
    const float4* __restrict__ A4,
    const float4* __restrict__ Bq4, const float4* __restrict__ Bk4,
    float* __restrict__ C, int m0, int n0, int cstride, int qk, int kc,
    float* sm)
{
    float4* As = (float4*)sm;            // [32][17] f4
    float4* Bs = (float4*)sm + 544;      // [32][17] f4
    const int tid  = threadIdx.x;
    const int lane = tid & 31;
    const int w    = tid >> 5;
    const int ng   = w & 3;
    const int kp   = w >> 2;

    float acc[8][2];
#pragma unroll
    for (int j = 0; j < 8; j++) { acc[j][0] = 0.f; acc[j][1] = 0.f; }

    const float4* Ap = As + lane*17 + kp;
    const float4* Bp = Bs + (ng*8)*17 + kp;

#pragma unroll
    for (int t = 0; t < 2; t++) {
        const int idx = tid + (t << 8);
        const int r = idx >> 4, c = idx & 15;
        As[r*17 + c] = A4[(m0 + r)*64 + (kc << 4) + c];
        int brow;
        const float4* bp;
        if (qk) {
            const int col = n0 + r;
            brow = ((col >> 3)*32) + (col & 3);
            bp = ((col >> 2) & 1) ? Bk4 : Bq4;
        } else {
            brow = n0 + r;
            bp = Bq4;
        }
        Bs[r*17 + c] = bp[brow*64 + (kc << 4) + c];
    }
    __syncthreads();

#pragma unroll
    for (int k4 = 0; k4 < 8; k4++) {
        const float4 a = Ap[k4*2];
#pragma unroll
        for (int j = 0; j < 8; j++) {
            const float4 b = Bp[j*17 + k4*2];
            acc[j][0] = fmaf(a.x, b.x, acc[j][0]);
            acc[j][1] = fmaf(a.y, b.y, acc[j][1]);
            acc[j][0] = fmaf(a.z, b.z, acc[j][0]);
            acc[j][1] = fmaf(a.w, b.w, acc[j][1]);
        }
    }
    __syncthreads();

    float* red = sm;
    if (kp == 1) {
#pragma unroll
        for (int j = 0; j < 8; j++) {
            red[(ng*32 + lane)*17 + j*2    ] = acc[j][0];
            red[(ng*32 + lane)*17 + j*2 + 1] = acc[j][1];
        }
    }
    __syncthreads();
    if (kp == 0) {
        const float* rp = &red[(ng*32 + lane)*17];
        float o[8];
#pragma unroll
        for (int j = 0; j < 8; j++)
            o[j] = acc[j][0] + acc[j][1] + rp[j*2] + rp[j*2 + 1];
        float* cp = &C[(m0 + lane)*cstride + n0 + ng*8];
        *(float4*)cp       = make_float4(o[0], o[1], o[2], o[3]);
        *(float4*)(cp + 4) = make_float4(o[4], o[5], o[6], o[7]);
    }
}

// ---------------------------------------------------------------------------
// Kernel 1: 656 blocks:
//   [0,512)   V-GEMM:  128 tiles x 4 K-quarters
//   [512,640) QK-GEMM:  32 tiles x 4 K-quarters
//   [640,656) bias-init: out[r][c] = bo[c]   (k2 REDG-accumulates onto this)
// ---------------------------------------------------------------------------
__global__ void __launch_bounds__(256, 4) k1_gemms(
    const float* __restrict__ x,
    const float* __restrict__ Wq, const float* __restrict__ Wk,
    const float* __restrict__ Wv,
    const float* __restrict__ bo, float* __restrict__ out)
{
    __shared__ float sm[4352];   // 17.4KB
    const int bx = blockIdx.x;
    if (bx < 512) {
        const int tile = bx >> 2, kc = bx & 3;
        gemm_q((const float4*)x, (const float4*)Wv, nullptr,
               g_Vp[kc], (tile >> 3) << 5, (tile & 7) << 5, 256, 0, kc, sm);
    } else if (bx < 640) {
        const int q = bx - 512;
        const int tile = q >> 2, kc = q & 3;
        gemm_q((const float4*)x, (const float4*)Wq, (const float4*)Wk,
               g_QKp[kc], (tile >> 1) << 5, (tile & 1) << 5, 64, 1, kc, sm);
    } else {
        const int t0 = (bx - 640)*256 + threadIdx.x;    // 0..4095
        float4* o4 = (float4*)out;
        const float4* b4 = (const float4*)bo;           // 64 float4
#pragma unroll
        for (int r = 0; r < 8; r++) {
            const int i = t0*8 + r;
            o4[i] = b4[i & 63];
        }
    }
}

// ---------------------------------------------------------------------------
// Kernel 2: fused attention + per-head rank-32 O-update.
// 128 blocks = (bh, 32-row i-group), 256 threads.
//  Phase 0: sum 4 V partials + bias into Vs; inline trig from QK partials.
//  Phase 1/2: proven single-pass softmax + o = softmax @ V -> AOs (smem).
//  Phase 3: out[i][n] += sum_{k<32} AOs[i][k] * Wo[n][32h+k]  via REDG.ADD
//           (out pre-filled with bo by k1; graph edge orders it).
// smem time-multiplexed: Ws (256x32 f) overlays Vs/CKs/E after phase 2.
// ---------------------------------------------------------------------------
__global__ void __launch_bounds__(256) attn_ofuse(
    const float* __restrict__ ap,
    const float* __restrict__ bq, const float* __restrict__ bk,
    const float* __restrict__ bv,
    const float* __restrict__ Wo, float* __restrict__ out)
{
    // float offsets into smu:
    //   Vs   [0,4096)      CKs [4096,4608)   AB  [4608,4800)
    //   E    [4800,9024)   Psum[9024,9312)   Sinv[9312,9344)
    //   AOs  [9344,10400)  Ws  [0,8192)  (after phase 2)
    __shared__ __align__(16) float smu[10400];   // 41.6KB
    float4* Vs   = (float4*)smu;             // [j][p]
    float4* CKs  = (float4*)(smu + 4096);    // [128]
    float*  AB   = smu + 4608;               // [32][6]
    float*  E    = smu + 4800;               // [128][33]
    float*  Psum = smu + 9024;               // [32][9]
    float*  Sinv = smu + 9312;               // [32]
    float*  AOs  = smu + 9344;               // [32][33]

    const int bx = blockIdx.x;
    const int ig = bx & 3;
    const int bh = bx >> 2;
    const int b = bh >> 3, h = bh & 7;

    const int tid  = threadIdx.x;
    const int lane = tid & 31;
    const int w    = tid >> 5;

    const float4* V0 = (const float4*)g_Vp[0];
    const float4* V1 = (const float4*)g_Vp[1];
    const float4* V2 = (const float4*)g_Vp[2];
    const float4* V3 = (const float4*)g_Vp[3];
#pragma unroll
    for (int t = 0; t < 4; t++) {
        const int idx = tid + (t << 8);
        const int j = idx >> 3, p = idx & 7;
        const int gi = (b*Sx + j)*64 + h*8 + p;
        const float4 a0 = V0[gi];
        const float4 a1 = V1[gi];
        const float4 a2 = V2[gi];
        const float4 a3 = V3[gi];
        const float4 bb = *(const float4*)&bv[h*32 + p*4];
        Vs[idx] = make_float4(a0.x + a1.x + a2.x + a3.x + bb.x,
                              a0.y + a1.y + a2.y + a3.y + bb.y,
                              a0.z + a1.z + a2.z + a3.z + bb.z,
                              a0.w + a1.w + a2.w + a3.w + bb.w);
    }

    const float PI = 3.14159265358979323846f;
    if (tid < 128) {
        // k-side trig for row j
        const int j = tid;
        const int base = (b*Sx + j)*64 + h*8 + 4;
        float v[4];
#pragma unroll
        for (int q = 0; q < 4; q++)
            v[q] = g_QKp[0][base + q] + g_QKp[1][base + q]
                 + g_QKp[2][base + q] + g_QKp[3][base + q] + bk[h*32 + q];
        const float mn = fminf(fminf(v[0], v[1]), fminf(v[2], v[3]));
        const float mx = fmaxf(fmaxf(v[0], v[1]), fmaxf(v[2], v[3]));
        const float sc = PI / (mx - mn + 1e-8f);
        CKs[j] = make_float4(cosf((v[1] - mn)*sc), cosf((v[2] - mn)*sc),
                             cosf((v[3] - mn)*sc), 0.f);
    } else if (tid < 160) {
        // q-side trig for row i
        const int il = tid - 128;
        const int i  = (ig << 5) + il;
        const int base = (b*Sx + i)*64 + h*8;
        float v[4];
#pragma unroll
        for (int q = 0; q < 4; q++)
            v[q] = g_QKp[0][base + q] + g_QKp[1][base + q]
                 + g_QKp[2][base + q] + g_QKp[3][base + q] + bq[h*32 + q];
        const float mn = fminf(fminf(v[0], v[1]), fminf(v[2], v[3]));
        const float mx = fmaxf(fmaxf(v[0], v[1]), fmaxf(v[2], v[3]));
        const float sc = PI / (mx - mn + 1e-8f);
#pragma unroll
        for (int wv = 0; wv < 3; wv++) {
            float sn, cs;
            sincosf((v[wv + 1] - mn)*sc, &sn, &cs);
            const float th = ap[wv + 1];
            AB[il*6 + wv*2 + 0] = cosf(th) * cs;
            AB[il*6 + wv*2 + 1] = sinf(th) * sn;
        }
    }
    __syncthreads();

    const int il = lane;

    // phase 1: exp scores; warp w handles 16 j's per il
    {
        const float A1 = AB[il*6+0], B1 = AB[il*6+1];
        const float A2 = AB[il*6+2], B2 = AB[il*6+3];
        const float A3 = AB[il*6+4], B3 = AB[il*6+5];
        const float SCALE = 0.17677669529663687f;   // 1/sqrt(32)
        float s = 0.f;
#pragma unroll
        for (int jj = 0; jj < 16; jj++) {
            const int j = (w << 4) + jj;
            const float4 ck = CKs[j];
            const float sc = (A1 - B1*ck.x) * (A2 - B2*ck.y) * (A3 - B3*ck.z);
            const float e = __expf(sc * SCALE);
            E[j*33 + il] = e;
            s += e;
        }
        Psum[il*9 + w] = s;
    }
    __syncthreads();
    if (tid < 32) {
        float s = 0.f;
#pragma unroll
        for (int jg = 0; jg < 8; jg++) s += Psum[tid*9 + jg];
        Sinv[tid] = 1.0f / s;
    }
    __syncthreads();

    // phase 2: p = warp owns one float4 dim-group; result -> AOs (smem)
    {
        const int p = w;
        float4 o = make_float4(0.f, 0.f, 0.f, 0.f);
#pragma unroll 8
        for (int j = 0; j < 128; j++) {
            const float e = E[j*33 + il];
            const float4 v = Vs[(j << 3) + p];
            o.x = fmaf(e, v.x, o.x);
            o.y = fmaf(e, v.y, o.y);
            o.z = fmaf(e, v.z, o.z);
            o.w = fmaf(e, v.w, o.w);
        }
        const float inv = Sinv[il];
        float* ar = &AOs[il*33 + p*4];
        ar[0] = o.x * inv;
        ar[1] = o.y * inv;
        ar[2] = o.z * inv;
        ar[3] = o.w * inv;
    }
    __syncthreads();   // AOs complete; Vs/CKs/E/Psum/Sinv now dead

    // phase 3a: stage Ws[n][k] = Wo[n][32h + k]  (256 x 32 floats over [0,8192))
    {
        float4* Ws4 = (float4*)smu;
        const float4* Wo4 = (const float4*)Wo;
#pragma unroll
        for (int t = 0; t < 8; t++) {
            const int idx = tid + (t << 8);      // 0..2047
            const int n = idx >> 3, c4 = idx & 7;
            Ws4[idx] = Wo4[n*64 + h*8 + c4];
        }
    }
    // load this lane's 32 AO values (row il, conflict-free stride-33 scalar LDS)
    float a[32];
#pragma unroll
    for (int k = 0; k < 32; k++) a[k] = AOs[il*33 + k];
    __syncthreads();

    // phase 3b: rank-32 update. Warp w covers n in [32w, 32w+32).
    {
        const float4* Ws4 = (const float4*)smu;
        const int grow = b*Sx + (ig << 5) + il;
        float* orow = &out[grow*256 + (w << 5)];
#pragma unroll
        for (int g = 0; g < 4; g++) {            // 8 n at a time
            float acc[8];
#pragma unroll
            for (int j = 0; j < 8; j++) acc[j] = 0.f;
#pragma unroll
            for (int k4 = 0; k4 < 8; k4++) {
                const float4 av = make_float4(a[k4*4], a[k4*4+1], a[k4*4+2], a[k4*4+3]);
#pragma unroll
                for (int j = 0; j < 8; j++) {
                    const float4 bv4 = Ws4[((w << 5) + g*8 + j)*8 + k4];
                    acc[j] = fmaf(av.x, bv4.x, acc[j]);
                    acc[j] = fmaf(av.y, bv4.y, acc[j]);
                    acc[j] = fmaf(av.z, bv4.z, acc[j]);
                    acc[j] = fmaf(av.w, bv4.w, acc[j]);
                }
            }
#pragma unroll
            for (int j = 0; j < 8; j++)
                atomicAdd(&orow[g*8 + j], acc[j]);   // REDG.ADD.F32 (no return)
        }
    }
}

// ---------------------------------------------------------------------------
extern "C" void kernel_launch(void* const* d_in, const int* in_sizes, int n_in,
                              void* d_out, int out_size)
{
    const float* x  = (const float*)d_in[0];
    const float* Wq = (const float*)d_in[1];
    const float* bq = (const float*)d_in[2];
    const float* Wk = (const float*)d_in[3];
    const float* bk = (const float*)d_in[4];
    const float* Wv = (const float*)d_in[5];
    const float* bv = (const float*)d_in[6];
    const float* Wo = (const float*)d_in[7];
    const float* bo = (const float*)d_in[8];
    const float* ap = (const float*)d_in[9];
    float* out = (float*)d_out;

    k1_gemms<<<656, 256>>>(x, Wq, Wk, Wv, bo, out);
    attn_ofuse<<<128, 256>>>(ap, bq, bk, bv, Wo, out);
}